// round 2
// baseline (speedup 1.0000x reference)
#include <cuda_runtime.h>
#include <math.h>

// TemplatePointwiseAttention fused kernel, fp32, warp-per-pair.
// Shapes: B=1, T=4, L=384, c_z=128, c_t=64, H=4, C=16.
//
// Per pair p=(i,j):
//   zn = LN(z[i,j,:])
//   q[n]    = zn . Wq[:,n]                              (n = h*16+c)
//   r[h][m] = sum_c q[h*16+c] * Wk[m][h*16+c]           (K-proj folded)
//   tn[t]   = LN(t[t,i,j,:])
//   logits[t,h] = (tn[t] . r[h]) * 0.25
//   masked softmax over t + renorm (matches reference exactly)
//   u[h][m] = sum_t attn[t,h] * tn[t][m]                (V-proj folded)
//   o[n]    = u[n/16] . Wv[:,n]
//   out     = o @ Wo + bo
//
// No dynamic smem, no cudaFuncSetAttribute (static smem 39.4 KB).
// Wq/Wv/Wo streamed coalesced from global (L1-resident); Wk in smem.
// z/t/out use streaming cache hints to protect weight residency in L1.

namespace {
constexpr int L_ = 384;
constexpr int NPAIR = L_ * L_;        // 147456
constexpr int WARPS = 8;
constexpr int NTHREADS = WARPS * 32;  // 256
constexpr int GRID = 152 * 4;         // 608 blocks, persistent grid-stride

// per-warp scratch layout (floats)
//   [0..271]    r_s   (4 x 68)  -> reused as u after softmax
//   [272..543]  tn_s  (4 x 68)  -> first 128 floats double as zn before t-LN
//   [544..607]  q_s   (64)
//   [608..623]  at_s  (16)
//   [624..687]  o_s   (64)
constexpr int SCR_W = 688;
constexpr int OFF_WK  = 0;                 // Wk[64][68]
constexpr int WK_FLOATS = 64 * 68;         // 4352
constexpr int OFF_SCR = WK_FLOATS;         // 4352
constexpr int SMEM_FLOATS = OFF_SCR + WARPS * SCR_W;   // 9856 -> 39424 B

__device__ __forceinline__ float dot4(float4 a, float4 b) {
    return fmaf(a.x, b.x, fmaf(a.y, b.y, fmaf(a.z, b.z, a.w * b.w)));
}
__device__ __forceinline__ float4 ldcs4(const float* p) {
    return __ldcs((const float4*)p);
}
__device__ __forceinline__ float2 ldcs2(const float* p) {
    return __ldcs((const float2*)p);
}
} // namespace

__global__ __launch_bounds__(NTHREADS) void tpa_fused(
    const float* __restrict__ tin,   // [4,384,384,64]
    const float* __restrict__ zin,   // [384,384,128]
    const float* __restrict__ mask,  // [4,384]
    const float* __restrict__ zg_,   // [128]
    const float* __restrict__ zb_,   // [128]
    const float* __restrict__ tg_,   // [64]
    const float* __restrict__ tb_,   // [64]
    const float* __restrict__ Wq,    // [128,64]
    const float* __restrict__ Wk,    // [64,64]
    const float* __restrict__ Wv,    // [64,64]
    const float* __restrict__ Wo,    // [64,128]
    const float* __restrict__ bo,    // [128]
    float* __restrict__ out)         // [384,384,128]
{
    __shared__ float sm[SMEM_FLOATS];
    const int tid = threadIdx.x;

    // stage Wk into smem: row m at stride 68 (conflict-free row-per-lane reads)
    for (int idx = tid; idx < 4096; idx += NTHREADS) {
        int m = idx >> 6, c = idx & 63;
        sm[OFF_WK + m * 68 + c] = Wk[idx];
    }
    __syncthreads();

    const int warp = tid >> 5, lane = tid & 31;
    float* scr  = sm + OFF_SCR + warp * SCR_W;
    float* r_s  = scr;            // 272 (r, later u)
    float* tn_s = scr + 272;      // 272 (zn overlay first 128 floats)
    float* zn_s = tn_s;           // overlay: zn dead before tn written
    float* q_s  = scr + 544;      // 64
    float* at_s = scr + 608;      // 16
    float* o_s  = scr + 624;      // 64

    // per-lane constants
    const float4 zg = *(const float4*)(zg_ + lane * 4);
    const float4 zb = *(const float4*)(zb_ + lane * 4);
    const float2 tg = *(const float2*)(tg_ + lane * 2);
    const float2 tb = *(const float2*)(tb_ + lane * 2);
    const float4 bo4 = *(const float4*)(bo + lane * 4);

    const int idx16 = lane & 15;
    const int half  = lane >> 4;     // 0/1: m-half for logit partial
    const int t_of  = idx16 >> 2;    // template idx for logits lane
    const int h_of  = idx16 & 3;     // head idx for logits lane
    const int h_o   = lane >> 3;     // head owned in o-stage (n = 2*lane)

    const int gw = blockIdx.x * WARPS + warp;
    const int nw = GRID * WARPS;

    for (int p = gw; p < NPAIR; p += nw) {
        const int i = p / L_;
        const int j = p - i * L_;

        // ---- streaming global loads (t issued early to hide latency) ----
        float4 zv = ldcs4(zin + (size_t)p * 128 + lane * 4);
        float2 tv[4];
        #pragma unroll
        for (int t = 0; t < 4; t++)
            tv[t] = ldcs2(tin + ((size_t)(t * L_ + i) * L_ + j) * 64 + lane * 2);

        // ---- z layernorm (lane owns 4 channels) ----
        {
            float s  = zv.x + zv.y + zv.z + zv.w;
            float ss = zv.x * zv.x + zv.y * zv.y + zv.z * zv.z + zv.w * zv.w;
            #pragma unroll
            for (int o = 16; o > 0; o >>= 1) {
                s  += __shfl_xor_sync(0xffffffffu, s,  o);
                ss += __shfl_xor_sync(0xffffffffu, ss, o);
            }
            float mu   = s * (1.0f / 128.0f);
            float var  = fmaf(ss, 1.0f / 128.0f, -mu * mu);
            float rstd = rsqrtf(var + 1e-5f);
            float4 znv;
            znv.x = (zv.x - mu) * rstd * zg.x + zb.x;
            znv.y = (zv.y - mu) * rstd * zg.y + zb.y;
            znv.z = (zv.z - mu) * rstd * zg.z + zb.z;
            znv.w = (zv.w - mu) * rstd * zg.w + zb.w;
            *(float4*)(zn_s + lane * 4) = znv;
        }
        __syncwarp();

        // ---- q[n] = zn . Wq[:,n]; lane owns n = 2*lane, 2*lane+1 ----
        // coalesced: each LDG.64 covers a full 64-float row of Wq across the warp
        {
            const float* wq = Wq + 2 * lane;
            float2 qa = make_float2(0.f, 0.f), qb = make_float2(0.f, 0.f);
            #pragma unroll
            for (int m = 0; m < 128; m += 2) {
                float2 zz = *(const float2*)(zn_s + m);   // broadcast
                float2 w0 = *(const float2*)(wq + m * 64);
                float2 w1 = *(const float2*)(wq + (m + 1) * 64);
                qa.x = fmaf(zz.x, w0.x, qa.x); qa.y = fmaf(zz.x, w0.y, qa.y);
                qb.x = fmaf(zz.y, w1.x, qb.x); qb.y = fmaf(zz.y, w1.y, qb.y);
            }
            *(float2*)(q_s + 2 * lane) = make_float2(qa.x + qb.x, qa.y + qb.y);
        }
        __syncwarp();

        // ---- r[h][m] = sum_c q[h*16+c] * Wk[m][h*16+c]; lane owns m=lane,lane+32 ----
        {
            const float* wk0 = sm + OFF_WK + lane * 68;
            const float* wk1 = wk0 + 32 * 68;
            #pragma unroll
            for (int h = 0; h < 4; h++) {
                float a0 = 0.f, a1 = 0.f;
                #pragma unroll
                for (int c = 0; c < 16; c += 4) {
                    float4 qv = *(const float4*)(q_s + h * 16 + c);
                    a0 += dot4(qv, *(const float4*)(wk0 + h * 16 + c));
                    a1 += dot4(qv, *(const float4*)(wk1 + h * 16 + c));
                }
                r_s[h * 68 + lane]      = a0;
                r_s[h * 68 + lane + 32] = a1;
            }
        }
        // zn is dead now; tn overlays its region
        __syncwarp();

        // ---- t layernorms (lane owns m = 2*lane, 2*lane+1) ----
        #pragma unroll
        for (int t = 0; t < 4; t++) {
            float s  = tv[t].x + tv[t].y;
            float ss = tv[t].x * tv[t].x + tv[t].y * tv[t].y;
            #pragma unroll
            for (int o = 16; o > 0; o >>= 1) {
                s  += __shfl_xor_sync(0xffffffffu, s,  o);
                ss += __shfl_xor_sync(0xffffffffu, ss, o);
            }
            float mu   = s * (1.0f / 64.0f);
            float var  = fmaf(ss, 1.0f / 64.0f, -mu * mu);
            float rstd = rsqrtf(var + 1e-5f);
            float2 tnv;
            tnv.x = (tv[t].x - mu) * rstd * tg.x + tb.x;
            tnv.y = (tv[t].y - mu) * rstd * tg.y + tb.y;
            *(float2*)(tn_s + t * 68 + lane * 2) = tnv;
        }
        __syncwarp();

        // ---- logits + masked softmax over t (lane (half,t,h) owns one partial) ----
        {
            const float* tnp = tn_s + t_of * 68 + half * 32;
            const float* rp  = r_s  + h_of * 68 + half * 32;
            float acc = 0.f;
            #pragma unroll
            for (int s4 = 0; s4 < 32; s4 += 4)
                acc += dot4(*(const float4*)(tnp + s4), *(const float4*)(rp + s4));
            acc += __shfl_xor_sync(0xffffffffu, acc, 16);   // combine m-halves
            float logit = acc * 0.25f;                       // 1/sqrt(C)

            float pm = mask[t_of * L_ + i] * mask[t_of * L_ + j];
            logit = (pm == 0.0f) ? -1e9f : logit;

            // reduce over t: xor 4 (t bit0), xor 8 (t bit1)
            float mx = fmaxf(logit, __shfl_xor_sync(0xffffffffu, logit, 4));
            mx = fmaxf(mx, __shfl_xor_sync(0xffffffffu, mx, 8));
            float e = __expf(logit - mx);
            float den = e + __shfl_xor_sync(0xffffffffu, e, 4);
            den += __shfl_xor_sync(0xffffffffu, den, 8);
            float attn = __fdividef(e, den) * pm;
            float s2 = attn + __shfl_xor_sync(0xffffffffu, attn, 4);
            s2 += __shfl_xor_sync(0xffffffffu, s2, 8);
            attn = __fdividef(attn, fmaxf(s2, 1e-8f));
            at_s[t_of * 4 + h_of] = attn;   // lanes l and l^16 write same value
        }
        __syncwarp();   // logits done reading r_s; at_s visible

        // ---- u[h][m] = sum_t attn[t,h]*tn[t][m]; lane owns m=lane,lane+32 ----
        {
            float u0[4] = {0.f, 0.f, 0.f, 0.f};
            float u1[4] = {0.f, 0.f, 0.f, 0.f};
            #pragma unroll
            for (int t = 0; t < 4; t++) {
                float a0 = tn_s[t * 68 + lane];
                float a1 = tn_s[t * 68 + lane + 32];
                #pragma unroll
                for (int h = 0; h < 4; h++) {
                    float a = at_s[t * 4 + h];   // broadcast
                    u0[h] = fmaf(a, a0, u0[h]);
                    u1[h] = fmaf(a, a1, u1[h]);
                }
            }
            #pragma unroll
            for (int h = 0; h < 4; h++) {
                r_s[h * 68 + lane]      = u0[h];   // overwrite r with u
                r_s[h * 68 + lane + 32] = u1[h];
            }
        }
        __syncwarp();

        // ---- o[n] = u[h(n)] . Wv[:,n]; lane owns n = 2*lane, 2*lane+1 ----
        {
            const float* up = r_s + h_o * 68;   // h = (2*lane)/16 = lane>>3
            const float* wv = Wv + 2 * lane;
            float2 oa = make_float2(0.f, 0.f), ob = make_float2(0.f, 0.f);
            #pragma unroll
            for (int m = 0; m < 64; m += 2) {
                float2 uu = *(const float2*)(up + m);    // 4-addr multicast
                float2 w0 = *(const float2*)(wv + m * 64);
                float2 w1 = *(const float2*)(wv + (m + 1) * 64);
                oa.x = fmaf(uu.x, w0.x, oa.x); oa.y = fmaf(uu.x, w0.y, oa.y);
                ob.x = fmaf(uu.y, w1.x, ob.x); ob.y = fmaf(uu.y, w1.y, ob.y);
            }
            *(float2*)(o_s + 2 * lane) = make_float2(oa.x + ob.x, oa.y + ob.y);
        }
        __syncwarp();

        // ---- res[j'] = o . Wo[:,j'] + bo; lane owns j' = 4*lane..4*lane+3 ----
        {
            const float* wo = Wo + 4 * lane;
            float4 a0 = bo4;
            float4 a1 = make_float4(0.f, 0.f, 0.f, 0.f);
            #pragma unroll
            for (int n = 0; n < 64; n += 2) {
                float2 oo = *(const float2*)(o_s + n);   // broadcast
                float4 w0 = *(const float4*)(wo + n * 128);
                float4 w1 = *(const float4*)(wo + (n + 1) * 128);
                a0.x = fmaf(oo.x, w0.x, a0.x); a0.y = fmaf(oo.x, w0.y, a0.y);
                a0.z = fmaf(oo.x, w0.z, a0.z); a0.w = fmaf(oo.x, w0.w, a0.w);
                a1.x = fmaf(oo.y, w1.x, a1.x); a1.y = fmaf(oo.y, w1.y, a1.y);
                a1.z = fmaf(oo.y, w1.z, a1.z); a1.w = fmaf(oo.y, w1.w, a1.w);
            }
            float4 res;
            res.x = a0.x + a1.x; res.y = a0.y + a1.y;
            res.z = a0.z + a1.z; res.w = a0.w + a1.w;
            __stcs((float4*)(out + (size_t)p * 128 + 4 * lane), res);
        }
        __syncwarp();   // scratch reuse barrier before next pair
    }
}

extern "C" void kernel_launch(void* const* d_in, const int* in_sizes, int n_in,
                              void* d_out, int out_size) {
    (void)in_sizes; (void)n_in; (void)out_size;
    tpa_fused<<<GRID, NTHREADS>>>(
        (const float*)d_in[0],  // t
        (const float*)d_in[1],  // z
        (const float*)d_in[2],  // template_mask
        (const float*)d_in[3],  // z_ln_g
        (const float*)d_in[4],  // z_ln_b
        (const float*)d_in[5],  // t_ln_g
        (const float*)d_in[6],  // t_ln_b
        (const float*)d_in[7],  // Wq
        (const float*)d_in[8],  // Wk
        (const float*)d_in[9],  // Wv
        (const float*)d_in[10], // Wo
        (const float*)d_in[11], // bo
        (float*)d_out);
}

// round 3
// speedup vs baseline: 2.9280x; 2.9280x over previous
#include <cuda_runtime.h>
#include <math.h>

// TemplatePointwiseAttention fused kernel, fp32, warp-per-4-pairs.
// Shapes: B=1, T=4, L=384, c_z=128, c_t=64, H=4, C=16.
//
// Per pair p=(i,j):
//   zn = LN(z[i,j,:]);  q[n] = zn . Wq[:,n]
//   r[h][m] = sum_c q[h*16+c] * Wk[m][h*16+c]      (K-proj folded, via WkT)
//   tn[t] = LN(t[t,i,j,:]);  logits[t,h] = (tn[t].r[h]) * 0.25
//   masked softmax over t + renorm;  u[h][m] = sum_t attn[t,h]*tn[t][m]
//   o[n] = u[n/16] . Wv[:,n];  out = o @ Wo + bo
//
// 4 pairs per warp iteration: every weight LDG feeds 4 FMA sets (4x less
// L1 weight traffic — R2 ncu showed l1tex 61% / fma 15% / dram 4%).
// Static smem only (44 KB). Wk pre-transposed into __device__ global.

namespace {
constexpr int L_ = 384;
constexpr int NPAIR = L_ * L_;        // 147456
constexpr int NP = 4;                 // pairs per warp iteration
constexpr int NB = NPAIR / NP;        // 36864 pair-blocks
constexpr int WARPS = 4;
constexpr int NTHREADS = WARPS * 32;  // 128
constexpr int GRID = 152 * 4;         // 608 blocks

// per-pair scratch (floats):
//   [0..271]   r_s  (4 x 68)  -> reused as u after softmax
//   [272..543] tn_s (4 x 68)  -> first 128 floats overlay zn
//   [544..607] q_s  (64)
//   [608..623] at_s (16)
//   [624..687] o_s  (64)
constexpr int SCR_P = 688;
constexpr int SCR_W = NP * SCR_P;                    // 2752 per warp
constexpr int SMEM_FLOATS = WARPS * SCR_W;           // 11008 -> 44032 B

__device__ float g_WkT[64 * 64];   // WkT[c][m] = Wk[m][c]

__device__ __forceinline__ float dot4(float4 a, float4 b) {
    return fmaf(a.x, b.x, fmaf(a.y, b.y, fmaf(a.z, b.z, a.w * b.w)));
}
__device__ __forceinline__ float4 ldcs4(const float* p) {
    return __ldcs((const float4*)p);
}
__device__ __forceinline__ float2 ldcs2(const float* p) {
    return __ldcs((const float2*)p);
}
} // namespace

__global__ void tpa_prep(const float* __restrict__ Wk) {
    int idx = blockIdx.x * blockDim.x + threadIdx.x;
    if (idx < 4096) {
        int m = idx >> 6, c = idx & 63;
        g_WkT[c * 64 + m] = Wk[idx];
    }
}

__global__ __launch_bounds__(NTHREADS, 4) void tpa_fused(
    const float* __restrict__ tin,   // [4,384,384,64]
    const float* __restrict__ zin,   // [384,384,128]
    const float* __restrict__ mask,  // [4,384]
    const float* __restrict__ zg_, const float* __restrict__ zb_,
    const float* __restrict__ tg_, const float* __restrict__ tb_,
    const float* __restrict__ Wq,    // [128,64]
    const float* __restrict__ Wv,    // [64,64]
    const float* __restrict__ Wo,    // [64,128]
    const float* __restrict__ bo,    // [128]
    float* __restrict__ out)         // [384,384,128]
{
    __shared__ float sm[SMEM_FLOATS];
    const int tid  = threadIdx.x;
    const int warp = tid >> 5, lane = tid & 31;
    float* scr = sm + warp * SCR_W;

    // per-lane constants
    const float4 zg = *(const float4*)(zg_ + lane * 4);
    const float4 zb = *(const float4*)(zb_ + lane * 4);
    const float2 tg = *(const float2*)(tg_ + lane * 2);
    const float2 tb = *(const float2*)(tb_ + lane * 2);
    const float4 bo4 = *(const float4*)(bo + lane * 4);

    const int idx16 = lane & 15;
    const int half  = lane >> 4;     // m-half for logit partial
    const int t_of  = idx16 >> 2;    // template idx (logits lane)
    const int h_of  = idx16 & 3;     // head idx (logits lane)
    const int h_o   = lane >> 3;     // head owned in o-stage (n = 2*lane)

    const int gw = blockIdx.x * WARPS + warp;
    const int nw = GRID * WARPS;

    for (int b = gw; b < NB; b += nw) {
        const int p0 = b * NP;
        const int i  = p0 / L_;          // all 4 pairs share row i
        const int j0 = p0 - i * L_;

        // ---- z loads + LN (per pair) ----
        #pragma unroll
        for (int k = 0; k < NP; k++) {
            float4 zv = ldcs4(zin + (size_t)(p0 + k) * 128 + lane * 4);
            float s  = zv.x + zv.y + zv.z + zv.w;
            float ss = zv.x * zv.x + zv.y * zv.y + zv.z * zv.z + zv.w * zv.w;
            #pragma unroll
            for (int o = 16; o > 0; o >>= 1) {
                s  += __shfl_xor_sync(0xffffffffu, s,  o);
                ss += __shfl_xor_sync(0xffffffffu, ss, o);
            }
            float mu   = s * (1.0f / 128.0f);
            float rstd = rsqrtf(fmaf(ss, 1.0f / 128.0f, -mu * mu) + 1e-5f);
            float4 znv;
            znv.x = (zv.x - mu) * rstd * zg.x + zb.x;
            znv.y = (zv.y - mu) * rstd * zg.y + zb.y;
            znv.z = (zv.z - mu) * rstd * zg.z + zb.z;
            znv.w = (zv.w - mu) * rstd * zg.w + zb.w;
            // zn overlays tn region (dead before tn written)
            *(float4*)(scr + k * SCR_P + 272 + lane * 4) = znv;
        }
        __syncwarp();

        // ---- prefetch t (streaming; consumed after q/r compute) ----
        float2 tv[NP][4];
        #pragma unroll
        for (int k = 0; k < NP; k++)
            #pragma unroll
            for (int t = 0; t < 4; t++)
                tv[k][t] = ldcs2(tin + ((size_t)(t * L_ + i) * L_ + (j0 + k)) * 64 + lane * 2);

        // ---- q[n] = zn . Wq[:,n]; lane owns n = 2*lane, 2*lane+1 ----
        {
            float2 qacc[NP];
            #pragma unroll
            for (int k = 0; k < NP; k++) qacc[k] = make_float2(0.f, 0.f);
            const float* wq = Wq + 2 * lane;
            #pragma unroll 8
            for (int m = 0; m < 128; m += 2) {
                float2 w0 = *(const float2*)(wq + m * 64);
                float2 w1 = *(const float2*)(wq + (m + 1) * 64);
                #pragma unroll
                for (int k = 0; k < NP; k++) {
                    float2 zz = *(const float2*)(scr + k * SCR_P + 272 + m);  // bcast
                    qacc[k].x = fmaf(zz.x, w0.x, fmaf(zz.y, w1.x, qacc[k].x));
                    qacc[k].y = fmaf(zz.x, w0.y, fmaf(zz.y, w1.y, qacc[k].y));
                }
            }
            #pragma unroll
            for (int k = 0; k < NP; k++)
                *(float2*)(scr + k * SCR_P + 544 + 2 * lane) = qacc[k];
        }
        __syncwarp();

        // ---- r[h][m] = sum_c q[h*16+c]*WkT[h*16+c][m]; lane owns m=2l,2l+1 ----
        #pragma unroll
        for (int h = 0; h < 4; h++) {
            float2 racc[NP];
            #pragma unroll
            for (int k = 0; k < NP; k++) racc[k] = make_float2(0.f, 0.f);
            #pragma unroll
            for (int c = 0; c < 16; c++) {
                float2 w = *(const float2*)(g_WkT + (h * 16 + c) * 64 + 2 * lane);
                #pragma unroll
                for (int k = 0; k < NP; k++) {
                    float qv = scr[k * SCR_P + 544 + h * 16 + c];   // bcast
                    racc[k].x = fmaf(qv, w.x, racc[k].x);
                    racc[k].y = fmaf(qv, w.y, racc[k].y);
                }
            }
            #pragma unroll
            for (int k = 0; k < NP; k++)
                *(float2*)(scr + k * SCR_P + h * 68 + 2 * lane) = racc[k];
        }
        __syncwarp();

        // ---- t layernorms (lane owns m = 2*lane, 2*lane+1) ----
        #pragma unroll
        for (int k = 0; k < NP; k++)
            #pragma unroll
            for (int t = 0; t < 4; t++) {
                float2 v = tv[k][t];
                float s  = v.x + v.y;
                float ss = v.x * v.x + v.y * v.y;
                #pragma unroll
                for (int o = 16; o > 0; o >>= 1) {
                    s  += __shfl_xor_sync(0xffffffffu, s,  o);
                    ss += __shfl_xor_sync(0xffffffffu, ss, o);
                }
                float mu   = s * (1.0f / 64.0f);
                float rstd = rsqrtf(fmaf(ss, 1.0f / 64.0f, -mu * mu) + 1e-5f);
                float2 tnv;
                tnv.x = (v.x - mu) * rstd * tg.x + tb.x;
                tnv.y = (v.y - mu) * rstd * tg.y + tb.y;
                *(float2*)(scr + k * SCR_P + 272 + t * 68 + lane * 2) = tnv;
            }
        __syncwarp();

        // ---- logits + masked softmax over t (per pair) ----
        #pragma unroll
        for (int k = 0; k < NP; k++) {
            const float* tnp = scr + k * SCR_P + 272 + t_of * 68 + half * 32;
            const float* rp  = scr + k * SCR_P + h_of * 68 + half * 32;
            float acc = 0.f;
            #pragma unroll
            for (int s4 = 0; s4 < 32; s4 += 4)
                acc += dot4(*(const float4*)(tnp + s4), *(const float4*)(rp + s4));
            acc += __shfl_xor_sync(0xffffffffu, acc, 16);
            float logit = acc * 0.25f;

            float pm = mask[t_of * L_ + i] * mask[t_of * L_ + j0 + k];
            logit = (pm == 0.0f) ? -1e9f : logit;

            float mx = fmaxf(logit, __shfl_xor_sync(0xffffffffu, logit, 4));
            mx = fmaxf(mx, __shfl_xor_sync(0xffffffffu, mx, 8));
            float e = __expf(logit - mx);
            float den = e + __shfl_xor_sync(0xffffffffu, e, 4);
            den += __shfl_xor_sync(0xffffffffu, den, 8);
            float attn = __fdividef(e, den) * pm;
            float s2 = attn + __shfl_xor_sync(0xffffffffu, attn, 4);
            s2 += __shfl_xor_sync(0xffffffffu, s2, 8);
            attn = __fdividef(attn, fmaxf(s2, 1e-8f));
            scr[k * SCR_P + 608 + t_of * 4 + h_of] = attn;  // l and l^16 same val
        }
        __syncwarp();

        // ---- u[h][m] = sum_t attn[t,h]*tn[t][m]; lane owns m=lane,lane+32 ----
        #pragma unroll
        for (int k = 0; k < NP; k++) {
            float* pk = scr + k * SCR_P;
            float u0[4] = {0.f, 0.f, 0.f, 0.f};
            float u1[4] = {0.f, 0.f, 0.f, 0.f};
            #pragma unroll
            for (int t = 0; t < 4; t++) {
                float  a0 = pk[272 + t * 68 + lane];
                float  a1 = pk[272 + t * 68 + lane + 32];
                float4 av = *(const float4*)(pk + 608 + t * 4);   // attn[t][0..3]
                u0[0] = fmaf(av.x, a0, u0[0]); u1[0] = fmaf(av.x, a1, u1[0]);
                u0[1] = fmaf(av.y, a0, u0[1]); u1[1] = fmaf(av.y, a1, u1[1]);
                u0[2] = fmaf(av.z, a0, u0[2]); u1[2] = fmaf(av.z, a1, u1[2]);
                u0[3] = fmaf(av.w, a0, u0[3]); u1[3] = fmaf(av.w, a1, u1[3]);
            }
            #pragma unroll
            for (int h = 0; h < 4; h++) {
                pk[h * 68 + lane]      = u0[h];   // overwrite r with u
                pk[h * 68 + lane + 32] = u1[h];
            }
        }
        __syncwarp();

        // ---- o[n] = u[h(n)] . Wv[:,n]; lane owns n = 2*lane, 2*lane+1 ----
        {
            float2 oacc[NP];
            #pragma unroll
            for (int k = 0; k < NP; k++) oacc[k] = make_float2(0.f, 0.f);
            const float* wv = Wv + 2 * lane;
            #pragma unroll 8
            for (int m = 0; m < 64; m += 2) {
                float2 w0 = *(const float2*)(wv + m * 64);
                float2 w1 = *(const float2*)(wv + (m + 1) * 64);
                #pragma unroll
                for (int k = 0; k < NP; k++) {
                    float2 uu = *(const float2*)(scr + k * SCR_P + h_o * 68 + m);
                    oacc[k].x = fmaf(uu.x, w0.x, fmaf(uu.y, w1.x, oacc[k].x));
                    oacc[k].y = fmaf(uu.x, w0.y, fmaf(uu.y, w1.y, oacc[k].y));
                }
            }
            #pragma unroll
            for (int k = 0; k < NP; k++)
                *(float2*)(scr + k * SCR_P + 624 + 2 * lane) = oacc[k];
        }
        __syncwarp();

        // ---- res[j'] = o . Wo[:,j'] + bo; lane owns j' = 4*lane..4*lane+3 ----
        {
            float4 acc[NP];
            #pragma unroll
            for (int k = 0; k < NP; k++) acc[k] = bo4;
            const float* wo = Wo + 4 * lane;
            #pragma unroll 8
            for (int n = 0; n < 64; n += 2) {
                float4 w0 = *(const float4*)(wo + n * 128);
                float4 w1 = *(const float4*)(wo + (n + 1) * 128);
                #pragma unroll
                for (int k = 0; k < NP; k++) {
                    float2 oo = *(const float2*)(scr + k * SCR_P + 624 + n);  // bcast
                    acc[k].x = fmaf(oo.x, w0.x, fmaf(oo.y, w1.x, acc[k].x));
                    acc[k].y = fmaf(oo.x, w0.y, fmaf(oo.y, w1.y, acc[k].y));
                    acc[k].z = fmaf(oo.x, w0.z, fmaf(oo.y, w1.z, acc[k].z));
                    acc[k].w = fmaf(oo.x, w0.w, fmaf(oo.y, w1.w, acc[k].w));
                }
            }
            #pragma unroll
            for (int k = 0; k < NP; k++)
                __stcs((float4*)(out + (size_t)(p0 + k) * 128 + 4 * lane), acc[k]);
        }
        __syncwarp();   // scratch reuse barrier before next block
    }
}

extern "C" void kernel_launch(void* const* d_in, const int* in_sizes, int n_in,
                              void* d_out, int out_size) {
    (void)in_sizes; (void)n_in; (void)out_size;
    tpa_prep<<<16, 256>>>((const float*)d_in[8]);   // Wk
    tpa_fused<<<GRID, NTHREADS>>>(
        (const float*)d_in[0],  // t
        (const float*)d_in[1],  // z
        (const float*)d_in[2],  // template_mask
        (const float*)d_in[3],  // z_ln_g
        (const float*)d_in[4],  // z_ln_b
        (const float*)d_in[5],  // t_ln_g
        (const float*)d_in[6],  // t_ln_b
        (const float*)d_in[7],  // Wq
        (const float*)d_in[9],  // Wv
        (const float*)d_in[10], // Wo
        (const float*)d_in[11], // bo
        (float*)d_out);
}